// round 2
// baseline (speedup 1.0000x reference)
#include <cuda_runtime.h>
#include <cstdint>
#include <cstddef>

// Problem sizes
#define BB   8192
#define II   1024
#define HH   1024
#define KK   2048          // I + H
#define NNP  4096          // 4*H packed (gate-interleaved)
// GEMM tiling
#define BM   128
#define BN   256
#define BK   32
#define NCHUNK (KK / BK)   // 64
#define THREADS 256
#define NSTAGE 3
#define ASTAGE_BYTES (BM * BK * 4)          // 16384
#define BSTAGE_BYTES (BN * BK * 4)          // 32768
#define STAGE_BYTES  (ASTAGE_BYTES + BSTAGE_BYTES)   // 49152
#define DYN_SMEM (NSTAGE * STAGE_BYTES)              // 147456

// Packed operands (tf32-rounded, K permuted within 8-groups as k0,k4,k1,k5,k2,k6,k3,k7)
__device__ float g_At[(size_t)BB * KK];   // [m][k'] rows of [x | h]
__device__ float g_Wt[(size_t)NNP * KK];  // [np][k'], np = 4*j + gate

// ---------------------------------------------------------------- helpers ---
__device__ __forceinline__ uint32_t smem_u32(const void* p) {
    uint32_t a;
    asm("{ .reg .u64 t; cvta.to.shared.u64 t, %1; cvt.u32.u64 %0, t; }"
        : "=r"(a) : "l"(p));
    return a;
}
__device__ __forceinline__ float tf32_rn(float x) {
    uint32_t r;
    asm("cvt.rna.tf32.f32 %0, %1;" : "=r"(r) : "r"(__float_as_uint(x)));
    return __uint_as_float(r);
}
__device__ __forceinline__ void cp_async16(uint32_t saddr, const void* gaddr) {
    asm volatile("cp.async.cg.shared.global [%0], [%1], 16;"
                 :: "r"(saddr), "l"(gaddr) : "memory");
}
__device__ __forceinline__ void cp_commit() {
    asm volatile("cp.async.commit_group;" ::: "memory");
}
__device__ __forceinline__ void cp_wait1() {
    asm volatile("cp.async.wait_group 1;" ::: "memory");
}
__device__ __forceinline__ void lds_v2(uint32_t& r0, uint32_t& r1, uint32_t addr) {
    asm volatile("ld.shared.v2.b32 {%0,%1}, [%2];"
                 : "=r"(r0), "=r"(r1) : "r"(addr));
}
__device__ __forceinline__ void mma_tf32(float* d, const uint32_t* a, const uint32_t* b) {
    asm volatile(
        "mma.sync.aligned.m16n8k8.row.col.f32.tf32.tf32.f32 "
        "{%0,%1,%2,%3}, {%4,%5,%6,%7}, {%8,%9}, {%0,%1,%2,%3};"
        : "+f"(d[0]), "+f"(d[1]), "+f"(d[2]), "+f"(d[3])
        : "r"(a[0]), "r"(a[1]), "r"(a[2]), "r"(a[3]), "r"(b[0]), "r"(b[1]));
}
__device__ __forceinline__ float sigmoid_f(float v) {
    return 1.0f / (1.0f + __expf(-v));
}
__device__ __forceinline__ float tanh_f(float v) {
    return 2.0f / (1.0f + __expf(-2.0f * v)) - 1.0f;
}
// K permutation within an 8-group: pos p holds source k = (p&1)*4 + (p>>1)
__device__ __forceinline__ int kperm_src(int p) { return ((p & 1) << 2) + (p >> 1); }

// ---------------------------------------------------------- pack A kernel ---
// g_At[m][d] = tf32( d<perm of x[m][*] for k<1024 else h[m][*] )
__global__ void pack_a_kernel(const float* __restrict__ x,
                              const float* __restrict__ h) {
    const int u = blockIdx.x * blockDim.x + threadIdx.x;   // float4 unit id
    const int row = u >> 9;                                // 512 units per row
    const int uu  = u & 511;
    const int d0  = uu * 4;
    float4 v;
    float* vp = reinterpret_cast<float*>(&v);
    #pragma unroll
    for (int i = 0; i < 4; i++) {
        const int d = d0 + i;
        const int k = (d & ~7) + kperm_src(d & 7);
        const float s = (k < II) ? x[(size_t)row * II + k]
                                 : h[(size_t)row * HH + (k - II)];
        vp[i] = tf32_rn(s);
    }
    *reinterpret_cast<float4*>(&g_At[(size_t)row * KK + d0]) = v;
}

// ---------------------------------------------------------- pack W kernel ---
// g_Wt[np][d]: np = 4*j + gate from source col c = gate*1024 + j of [Wx;Wh],
// K permuted within 8-groups, tf32-rounded.
__global__ void pack_w_kernel(const float* __restrict__ Wx,
                              const float* __restrict__ Wh) {
    __shared__ float tile[32][33];
    const int k0 = blockIdx.x * 32;
    const int c0 = blockIdx.y * 32;
    const int tx = threadIdx.x, ty = threadIdx.y;
    #pragma unroll
    for (int r = 0; r < 4; r++) {
        const int k = k0 + ty + 8 * r;
        const int c = c0 + tx;
        const float v = (k < II) ? Wx[(size_t)k * NNP + c]
                                 : Wh[(size_t)(k - II) * NNP + c];
        tile[ty + 8 * r][tx] = tf32_rn(v);
    }
    __syncthreads();
    #pragma unroll
    for (int r = 0; r < 4; r++) {
        const int c = c0 + ty + 8 * r;
        const int g = c >> 10;
        const int j = c & 1023;
        const int np = 4 * j + g;
        // dest col: permute tx within its 8-group: p(k) = (k&3)*2 + ((k>>2)&1)
        const int d = (tx & ~7) + ((tx & 3) * 2) + ((tx >> 2) & 1);
        g_Wt[(size_t)np * KK + k0 + d] = tile[tx][ty + 8 * r];
    }
}

// ------------------------------------------------------------ GEMM kernel ---
__global__ __launch_bounds__(THREADS) void lstm_gemm_kernel(
    const float* __restrict__ cin, const float* __restrict__ bx,
    float* __restrict__ out, int write_c) {
    extern __shared__ char dynsmem[];
    const uint32_t sbase = smem_u32(dynsmem);

    const int tid = threadIdx.x;
    const int wid = tid >> 5;
    const int lane = tid & 31;
    const int tn = blockIdx.x;       // N tile (0..15), 256 packed cols
    const int tm = blockIdx.y;       // M tile (0..63)
    const int row0 = tm * BM;
    const int n0 = tn * BN;

    float acc[4][8][4] = {};          // warp tile 64x64

    // ---- cp.async stage issue ----
    auto issue_stage = [&](int kc) {
        if (kc < NCHUNK) {
            const uint32_t sa = sbase + (kc % NSTAGE) * STAGE_BYTES;
            const uint32_t sb = sa + ASTAGE_BYTES;
            const float* gA = g_At + (size_t)row0 * KK + kc * BK;
            #pragma unroll
            for (int i = 0; i < 4; i++) {
                const int idx = tid + THREADS * i;   // 0..1023
                const int r = idx >> 3, uu = idx & 7;
                const uint32_t dst = sa + r * 128 + ((uu ^ (r & 7)) << 4);
                cp_async16(dst, gA + (size_t)r * KK + uu * 4);
            }
            const float* gB = g_Wt + (size_t)n0 * KK + kc * BK;
            #pragma unroll
            for (int i = 0; i < 8; i++) {
                const int idx = tid + THREADS * i;   // 0..2047
                const int r = idx >> 3, uu = idx & 7;
                const uint32_t dst = sb + r * 128 + ((uu ^ (r & 7)) << 4);
                cp_async16(dst, gB + (size_t)r * KK + uu * 4);
            }
        }
        cp_commit();
    };

    issue_stage(0);
    issue_stage(1);

    const int wm0 = (wid >> 2) * 64;   // warp M origin (0 or 64)
    const int wn0 = (wid & 3) * 64;    // warp N origin (0,64,128,192)

    #pragma unroll 1
    for (int kc = 0; kc < NCHUNK; kc++) {
        cp_wait1();
        __syncthreads();
        issue_stage(kc + 2);

        const uint32_t sa = sbase + (kc % NSTAGE) * STAGE_BYTES;
        const uint32_t sb = sa + ASTAGE_BYTES;

        #pragma unroll
        for (int s = 0; s < 4; s++) {
            // fragment unit index within row: lu = s*2 + ((lane&3)>>1), 8B half = lane&1
            const uint32_t lu = (uint32_t)(s * 2 + ((lane & 3) >> 1));
            const uint32_t half8 = (uint32_t)((lane & 1) << 3);

            uint32_t afr[4][4];
            #pragma unroll
            for (int mi = 0; mi < 4; mi++) {
                const int r = wm0 + mi * 16 + (lane >> 2);
                const uint32_t a_lo = sa + r * 128 + ((lu ^ (uint32_t)(r & 7)) << 4) + half8;
                lds_v2(afr[mi][0], afr[mi][2], a_lo);
                lds_v2(afr[mi][1], afr[mi][3], a_lo + 8 * 128);
            }
            uint32_t bfr[8][2];
            #pragma unroll
            for (int f = 0; f < 8; f++) {
                const int rn = wn0 + f * 8 + (lane >> 2);
                const uint32_t b_ad = sb + rn * 128 + ((lu ^ (uint32_t)(rn & 7)) << 4) + half8;
                lds_v2(bfr[f][0], bfr[f][1], b_ad);
            }
            #pragma unroll
            for (int mi = 0; mi < 4; mi++)
                #pragma unroll
                for (int f = 0; f < 8; f++)
                    mma_tf32(acc[mi][f], afr[mi], bfr[f]);
        }
    }

    __syncthreads();   // pipeline stages dead; reuse smem for output staging

    // ---- fused LSTM epilogue ----
    float* smf = reinterpret_cast<float*>(dynsmem);   // h_s[128][65], c_s[128][65]
    const int odd = lane & 1;
    #pragma unroll
    for (int mi = 0; mi < 4; mi++) {
        #pragma unroll
        for (int f = 0; f < 8; f++) {
            const float c0 = acc[mi][f][0], c1 = acc[mi][f][1];
            const float c2 = acc[mi][f][2], c3 = acc[mi][f][3];
            const float x0 = __shfl_xor_sync(0xffffffffu, c0, 1);
            const float x1 = __shfl_xor_sync(0xffffffffu, c1, 1);
            const float x2 = __shfl_xor_sync(0xffffffffu, c2, 1);
            const float x3 = __shfl_xor_sync(0xffffffffu, c3, 1);
            // even lane: row r, has (i,f)=c0,c1, partner's (g,o)=x0,x1
            // odd  lane: row r+8, has (g,o)=c2,c3, partner's (i,f)=x2,x3
            const int lrow = wm0 + mi * 16 + (lane >> 2) + (odd ? 8 : 0);
            const int jc = (wn0 >> 2) + f * 2 + ((lane & 3) >> 1);  // 0..63
            const int j = tn * 64 + jc;
            float gi = (odd ? x2 : c0) + bx[j];
            float gf = (odd ? x3 : c1) + bx[HH + j];
            float gg = (odd ? c2 : x0) + bx[2 * HH + j];
            float go = (odd ? c3 : x1) + bx[3 * HH + j];
            const float iv = sigmoid_f(gi);
            const float fv = sigmoid_f(gf);
            const float gv = tanh_f(gg);
            const float ov = sigmoid_f(go);
            const float cn = fv * cin[(size_t)(row0 + lrow) * HH + j] + iv * gv;
            const float hn = ov * tanh_f(cn);
            smf[lrow * 65 + jc] = hn;
            smf[128 * 65 + lrow * 65 + jc] = cn;
        }
    }
    __syncthreads();

    // coalesced writeback
    #pragma unroll 1
    for (int i = tid; i < 128 * 64; i += THREADS) {
        const int r = i >> 6, jj = i & 63;
        out[(size_t)(row0 + r) * HH + tn * 64 + jj] = smf[r * 65 + jj];
    }
    if (write_c) {
        #pragma unroll 1
        for (int i = tid; i < 128 * 64; i += THREADS) {
            const int r = i >> 6, jj = i & 63;
            out[(size_t)BB * HH + (size_t)(row0 + r) * HH + tn * 64 + jj] =
                smf[128 * 65 + r * 65 + jj];
        }
    }
}

// ------------------------------------------------------------------ launch ---
extern "C" void kernel_launch(void* const* d_in, const int* in_sizes, int n_in,
                              void* d_out, int out_size) {
    const float* x  = (const float*)d_in[0];
    const float* h  = (const float*)d_in[1];
    const float* c  = (const float*)d_in[2];
    const float* Wx = (const float*)d_in[3];
    const float* bx = (const float*)d_in[4];
    const float* Wh = (const float*)d_in[5];
    float* out = (float*)d_out;
    (void)in_sizes; (void)n_in;

    const int write_c = (out_size >= 2 * BB * HH) ? 1 : 0;

    // 1) pack operands (tf32 RN round + K-permute; W also transposed + gate-interleaved)
    pack_a_kernel<<<(BB * (KK / 4)) / THREADS, THREADS>>>(x, h);
    pack_w_kernel<<<dim3(KK / 32, NNP / 32), dim3(32, 8)>>>(Wx, Wh);

    // 2) tf32 mma.sync GEMM with fused LSTM epilogue
    static int attr_set = 0;
    if (!attr_set) {
        cudaFuncSetAttribute(lstm_gemm_kernel,
                             cudaFuncAttributeMaxDynamicSharedMemorySize, DYN_SMEM);
        attr_set = 1;
    }
    lstm_gemm_kernel<<<dim3(NNP / BN, BB / BM), THREADS, DYN_SMEM>>>(c, bx, out, write_c);
}

// round 3
// speedup vs baseline: 1.9026x; 1.9026x over previous
#include <cuda_runtime.h>
#include <cuda_fp16.h>
#include <cstdint>
#include <cstddef>

// Problem sizes
#define BB   8192
#define II   1024
#define HH   1024
#define KK   2048          // I + H
#define NNP  4096          // 4*H packed (gate-interleaved)
// GEMM tiling
#define BM   128
#define BN   256
#define BK   64            // fp16 elems per chunk (= 128 bytes per row)
#define NCHUNK (KK / BK)   // 32
#define THREADS 256
#define NSTAGE 3
#define ASTAGE_BYTES (BM * BK * 2)          // 16384
#define BSTAGE_BYTES (BN * BK * 2)          // 32768
#define STAGE_BYTES  (ASTAGE_BYTES + BSTAGE_BYTES)   // 49152
#define DYN_SMEM (NSTAGE * STAGE_BYTES)              // 147456

// Packed fp16 operands
__device__ __half g_At[(size_t)BB * KK];   // [m][k] rows of [x | h]
__device__ __half g_Wt[(size_t)NNP * KK];  // [np][k], np = 4*j + gate

// ---------------------------------------------------------------- helpers ---
__device__ __forceinline__ uint32_t smem_u32(const void* p) {
    uint32_t a;
    asm("{ .reg .u64 t; cvta.to.shared.u64 t, %1; cvt.u32.u64 %0, t; }"
        : "=r"(a) : "l"(p));
    return a;
}
__device__ __forceinline__ void cp_async16(uint32_t saddr, const void* gaddr) {
    asm volatile("cp.async.cg.shared.global [%0], [%1], 16;"
                 :: "r"(saddr), "l"(gaddr) : "memory");
}
__device__ __forceinline__ void cp_commit() {
    asm volatile("cp.async.commit_group;" ::: "memory");
}
__device__ __forceinline__ void cp_wait1() {
    asm volatile("cp.async.wait_group 1;" ::: "memory");
}
__device__ __forceinline__ void ldmatrix_x4(uint32_t* r, uint32_t addr) {
    asm volatile("ldmatrix.sync.aligned.m8n8.x4.shared.b16 {%0,%1,%2,%3}, [%4];"
                 : "=r"(r[0]), "=r"(r[1]), "=r"(r[2]), "=r"(r[3]) : "r"(addr));
}
__device__ __forceinline__ void mma_fp16(float* d, const uint32_t* a, const uint32_t* b) {
    asm volatile(
        "mma.sync.aligned.m16n8k16.row.col.f32.f16.f16.f32 "
        "{%0,%1,%2,%3}, {%4,%5,%6,%7}, {%8,%9}, {%0,%1,%2,%3};"
        : "+f"(d[0]), "+f"(d[1]), "+f"(d[2]), "+f"(d[3])
        : "r"(a[0]), "r"(a[1]), "r"(a[2]), "r"(a[3]), "r"(b[0]), "r"(b[1]));
}
__device__ __forceinline__ float sigmoid_f(float v) {
    return 1.0f / (1.0f + __expf(-v));
}
__device__ __forceinline__ float tanh_f(float v) {
    return 2.0f / (1.0f + __expf(-2.0f * v)) - 1.0f;
}

// ---------------------------------------------------------- pack A kernel ---
// g_At[m][k] = fp16( k<1024 ? x[m][k] : h[m][k-1024] ), 8 elems per thread
__global__ void pack_a_kernel(const float* __restrict__ x,
                              const float* __restrict__ h) {
    const int u = blockIdx.x * blockDim.x + threadIdx.x;   // 8-elem unit
    const int row = u >> 8;                                // 256 units per row
    const int k0 = (u & 255) * 8;
    const float* src = (k0 < II) ? (x + (size_t)row * II + k0)
                                 : (h + (size_t)row * HH + (k0 - II));
    const float4 v0 = *reinterpret_cast<const float4*>(src);
    const float4 v1 = *reinterpret_cast<const float4*>(src + 4);
    __half2 o[4];
    o[0] = __floats2half2_rn(v0.x, v0.y);
    o[1] = __floats2half2_rn(v0.z, v0.w);
    o[2] = __floats2half2_rn(v1.x, v1.y);
    o[3] = __floats2half2_rn(v1.z, v1.w);
    *reinterpret_cast<uint4*>(&g_At[(size_t)row * KK + k0]) =
        *reinterpret_cast<const uint4*>(o);
}

// ---------------------------------------------------------- pack W kernel ---
// g_Wt[np][k]: np = 4*j + gate from source col c = gate*1024 + j of [Wx;Wh]
__global__ void pack_w_kernel(const float* __restrict__ Wx,
                              const float* __restrict__ Wh) {
    __shared__ float tile[32][33];
    const int k0 = blockIdx.x * 32;
    const int c0 = blockIdx.y * 32;
    const int tx = threadIdx.x, ty = threadIdx.y;
    #pragma unroll
    for (int r = 0; r < 4; r++) {
        const int k = k0 + ty + 8 * r;
        const int c = c0 + tx;
        tile[ty + 8 * r][tx] = (k < II) ? Wx[(size_t)k * NNP + c]
                                        : Wh[(size_t)(k - II) * NNP + c];
    }
    __syncthreads();
    #pragma unroll
    for (int r = 0; r < 4; r++) {
        const int c = c0 + ty + 8 * r;
        const int g = c >> 10;
        const int j = c & 1023;
        const int np = 4 * j + g;
        g_Wt[(size_t)np * KK + k0 + tx] = __float2half_rn(tile[tx][ty + 8 * r]);
    }
}

// ------------------------------------------------------------ GEMM kernel ---
__global__ __launch_bounds__(THREADS) void lstm_gemm_kernel(
    const float* __restrict__ cin, const float* __restrict__ bx,
    float* __restrict__ out, int write_c) {
    extern __shared__ char dynsmem[];
    const uint32_t sbase = smem_u32(dynsmem);

    const int tid = threadIdx.x;
    const int wid = tid >> 5;
    const int lane = tid & 31;
    const int tn = blockIdx.x;       // N tile (0..15), 256 packed cols
    const int tm = blockIdx.y;       // M tile (0..63)
    const int row0 = tm * BM;
    const int n0 = tn * BN;

    float acc[4][8][4] = {};          // warp tile 64x64

    // ---- cp.async stage issue: rows of 64 fp16 = 128B, XOR-16B swizzle ----
    auto issue_stage = [&](int kc) {
        if (kc < NCHUNK) {
            const uint32_t sa = sbase + (kc % NSTAGE) * STAGE_BYTES;
            const uint32_t sb = sa + ASTAGE_BYTES;
            const __half* gA = g_At + (size_t)row0 * KK + kc * BK;
            #pragma unroll
            for (int i = 0; i < 4; i++) {
                const int idx = tid + THREADS * i;   // 0..1023 (128 rows x 8 units)
                const int r = idx >> 3, uu = idx & 7;
                const uint32_t dst = sa + r * 128 + ((uu ^ (r & 7)) << 4);
                cp_async16(dst, gA + (size_t)r * KK + uu * 8);
            }
            const __half* gB = g_Wt + (size_t)n0 * KK + kc * BK;
            #pragma unroll
            for (int i = 0; i < 8; i++) {
                const int idx = tid + THREADS * i;   // 0..2047 (256 rows x 8 units)
                const int r = idx >> 3, uu = idx & 7;
                const uint32_t dst = sb + r * 128 + ((uu ^ (r & 7)) << 4);
                cp_async16(dst, gB + (size_t)r * KK + uu * 8);
            }
        }
        cp_commit();
    };

    issue_stage(0);
    issue_stage(1);

    const int wm0 = (wid >> 2) * 64;   // warp M origin (0 or 64)
    const int wn0 = (wid & 3) * 64;    // warp N origin (0,64,128,192)
    const int lsel = lane >> 3;        // ldmatrix matrix id (0..3)
    const int lrow8 = lane & 7;        // row within 8x8 matrix

    #pragma unroll 1
    for (int kc = 0; kc < NCHUNK; kc++) {
        cp_wait1();
        __syncthreads();
        issue_stage(kc + 2);

        const uint32_t sa = sbase + (kc % NSTAGE) * STAGE_BYTES;
        const uint32_t sb = sa + ASTAGE_BYTES;

        #pragma unroll
        for (int s = 0; s < 4; s++) {           // 4 K-steps of 16 fp16
            uint32_t afr[4][4];
            #pragma unroll
            for (int mi = 0; mi < 4; mi++) {
                // m0:a0(r,kLo) m1:a1(r+8,kLo) m2:a2(r,kHi) m3:a3(r+8,kHi)
                const int r = wm0 + mi * 16 + (lsel & 1) * 8 + lrow8;
                const uint32_t ku = (uint32_t)(s * 2 + (lsel >> 1));
                ldmatrix_x4(afr[mi], sa + r * 128 + ((ku ^ (uint32_t)(r & 7)) << 4));
            }
            uint32_t bfr[4][4];                  // [fpair][b0,b1 of f=2fp | f=2fp+1]
            #pragma unroll
            for (int fp = 0; fp < 4; fp++) {
                // m0:(n,kLo) m1:(n,kHi) m2:(n+8,kLo) m3:(n+8,kHi)
                const int rn = wn0 + fp * 16 + (lsel >> 1) * 8 + lrow8;
                const uint32_t ku = (uint32_t)(s * 2 + (lsel & 1));
                ldmatrix_x4(bfr[fp], sb + rn * 128 + ((ku ^ (uint32_t)(rn & 7)) << 4));
            }
            #pragma unroll
            for (int mi = 0; mi < 4; mi++)
                #pragma unroll
                for (int f = 0; f < 8; f++)
                    mma_fp16(acc[mi][f], afr[mi], &bfr[f >> 1][(f & 1) * 2]);
        }
    }

    __syncthreads();   // pipeline stages dead; reuse smem for output staging

    // ---- fused LSTM epilogue (C layout identical to tf32 m16n8k8) ----
    float* smf = reinterpret_cast<float*>(dynsmem);   // h_s[128][65], c_s[128][65]
    const int odd = lane & 1;
    #pragma unroll
    for (int mi = 0; mi < 4; mi++) {
        #pragma unroll
        for (int f = 0; f < 8; f++) {
            const float c0 = acc[mi][f][0], c1 = acc[mi][f][1];
            const float c2 = acc[mi][f][2], c3 = acc[mi][f][3];
            const float x0 = __shfl_xor_sync(0xffffffffu, c0, 1);
            const float x1 = __shfl_xor_sync(0xffffffffu, c1, 1);
            const float x2 = __shfl_xor_sync(0xffffffffu, c2, 1);
            const float x3 = __shfl_xor_sync(0xffffffffu, c3, 1);
            // even lane: row g, own (i,f), partner's (g,o); odd: row g+8
            const int lrow = wm0 + mi * 16 + (lane >> 2) + (odd ? 8 : 0);
            const int jc = (wn0 >> 2) + f * 2 + ((lane & 3) >> 1);  // 0..63
            const int j = tn * 64 + jc;
            float gi = (odd ? x2 : c0) + bx[j];
            float gf = (odd ? x3 : c1) + bx[HH + j];
            float gg = (odd ? c2 : x0) + bx[2 * HH + j];
            float go = (odd ? c3 : x1) + bx[3 * HH + j];
            const float iv = sigmoid_f(gi);
            const float fv = sigmoid_f(gf);
            const float gv = tanh_f(gg);
            const float ov = sigmoid_f(go);
            const float cn = fv * cin[(size_t)(row0 + lrow) * HH + j] + iv * gv;
            const float hn = ov * tanh_f(cn);
            smf[lrow * 65 + jc] = hn;
            smf[128 * 65 + lrow * 65 + jc] = cn;
        }
    }
    __syncthreads();

    // coalesced writeback
    #pragma unroll 1
    for (int i = tid; i < 128 * 64; i += THREADS) {
        const int r = i >> 6, jj = i & 63;
        out[(size_t)(row0 + r) * HH + tn * 64 + jj] = smf[r * 65 + jj];
    }
    if (write_c) {
        #pragma unroll 1
        for (int i = tid; i < 128 * 64; i += THREADS) {
            const int r = i >> 6, jj = i & 63;
            out[(size_t)BB * HH + (size_t)(row0 + r) * HH + tn * 64 + jj] =
                smf[128 * 65 + r * 65 + jj];
        }
    }
}

// ------------------------------------------------------------------ launch ---
extern "C" void kernel_launch(void* const* d_in, const int* in_sizes, int n_in,
                              void* d_out, int out_size) {
    const float* x  = (const float*)d_in[0];
    const float* h  = (const float*)d_in[1];
    const float* c  = (const float*)d_in[2];
    const float* Wx = (const float*)d_in[3];
    const float* bx = (const float*)d_in[4];
    const float* Wh = (const float*)d_in[5];
    float* out = (float*)d_out;
    (void)in_sizes; (void)n_in;

    const int write_c = (out_size >= 2 * BB * HH) ? 1 : 0;

    // 1) pack operands to fp16 (W also transposed + gate-interleaved)
    pack_a_kernel<<<(BB * (KK / 8)) / THREADS, THREADS>>>(x, h);
    pack_w_kernel<<<dim3(KK / 32, NNP / 32), dim3(32, 8)>>>(Wx, Wh);

    // 2) fp16 mma.sync GEMM with fused LSTM epilogue
    static int attr_set = 0;
    if (!attr_set) {
        cudaFuncSetAttribute(lstm_gemm_kernel,
                             cudaFuncAttributeMaxDynamicSharedMemorySize, DYN_SMEM);
        attr_set = 1;
    }
    lstm_gemm_kernel<<<dim3(NNP / BN, BB / BM), THREADS, DYN_SMEM>>>(c, bx, out, write_c);
}

// round 5
// speedup vs baseline: 2.0969x; 1.1021x over previous
#include <cuda_runtime.h>
#include <cuda_fp16.h>
#include <cstdint>
#include <cstddef>

// Problem sizes
#define BB   8192
#define II   1024
#define HH   1024
#define KK   2048          // I + H
#define NNP  4096          // 4*H packed (gate-interleaved)
// GEMM tiling: CTA 128x128, 4 warps of 64x64, 2 CTAs/SM
#define BM   128
#define BN   128
#define BK   64            // fp16 elems per chunk (= 128 bytes per row)
#define NCHUNK (KK / BK)   // 32
#define THREADS 128
#define NSTAGE 3
#define ASTAGE_BYTES (BM * BK * 2)          // 16384
#define BSTAGE_BYTES (BN * BK * 2)          // 16384
#define STAGE_BYTES  (ASTAGE_BYTES + BSTAGE_BYTES)   // 32768
#define DYN_SMEM (NSTAGE * STAGE_BYTES)              // 98304

// Packed fp16 operands
__device__ __half g_At[(size_t)BB * KK];   // [m][k] rows of [x | h]
__device__ __half g_Wt[(size_t)NNP * KK];  // [np][k], np = 4*j + gate

// ---------------------------------------------------------------- helpers ---
__device__ __forceinline__ uint32_t smem_u32(const void* p) {
    uint32_t a;
    asm("{ .reg .u64 t; cvta.to.shared.u64 t, %1; cvt.u32.u64 %0, t; }"
        : "=r"(a) : "l"(p));
    return a;
}
__device__ __forceinline__ void cp_async16(uint32_t saddr, const void* gaddr) {
    asm volatile("cp.async.cg.shared.global [%0], [%1], 16;"
                 :: "r"(saddr), "l"(gaddr) : "memory");
}
__device__ __forceinline__ void cp_commit() {
    asm volatile("cp.async.commit_group;" ::: "memory");
}
__device__ __forceinline__ void cp_wait1() {
    asm volatile("cp.async.wait_group 1;" ::: "memory");
}
__device__ __forceinline__ void ldmatrix_x4(uint32_t* r, uint32_t addr) {
    asm volatile("ldmatrix.sync.aligned.m8n8.x4.shared.b16 {%0,%1,%2,%3}, [%4];"
                 : "=r"(r[0]), "=r"(r[1]), "=r"(r[2]), "=r"(r[3]) : "r"(addr));
}
__device__ __forceinline__ void mma_fp16(float* d, const uint32_t* a, const uint32_t* b) {
    asm volatile(
        "mma.sync.aligned.m16n8k16.row.col.f32.f16.f16.f32 "
        "{%0,%1,%2,%3}, {%4,%5,%6,%7}, {%8,%9}, {%0,%1,%2,%3};"
        : "+f"(d[0]), "+f"(d[1]), "+f"(d[2]), "+f"(d[3])
        : "r"(a[0]), "r"(a[1]), "r"(a[2]), "r"(a[3]), "r"(b[0]), "r"(b[1]));
}
__device__ __forceinline__ float sigmoid_f(float v) {
    return 1.0f / (1.0f + __expf(-v));
}
__device__ __forceinline__ float tanh_f(float v) {
    return 2.0f / (1.0f + __expf(-2.0f * v)) - 1.0f;
}

// ---------------------------------------------------------- pack A kernel ---
__global__ void pack_a_kernel(const float* __restrict__ x,
                              const float* __restrict__ h) {
    const int u = blockIdx.x * blockDim.x + threadIdx.x;   // 8-elem unit
    const int row = u >> 8;                                // 256 units per row
    const int k0 = (u & 255) * 8;
    const float* src = (k0 < II) ? (x + (size_t)row * II + k0)
                                 : (h + (size_t)row * HH + (k0 - II));
    const float4 v0 = *reinterpret_cast<const float4*>(src);
    const float4 v1 = *reinterpret_cast<const float4*>(src + 4);
    __half2 o[4];
    o[0] = __floats2half2_rn(v0.x, v0.y);
    o[1] = __floats2half2_rn(v0.z, v0.w);
    o[2] = __floats2half2_rn(v1.x, v1.y);
    o[3] = __floats2half2_rn(v1.z, v1.w);
    *reinterpret_cast<uint4*>(&g_At[(size_t)row * KK + k0]) =
        *reinterpret_cast<const uint4*>(o);
}

// ---------------------------------------------------------- pack W kernel ---
// g_Wt[np][k]: np = 4*j + gate from source col c = gate*1024 + j of [Wx;Wh]
__global__ void pack_w_kernel(const float* __restrict__ Wx,
                              const float* __restrict__ Wh) {
    __shared__ float tile[32][33];
    const int k0 = blockIdx.x * 32;
    const int c0 = blockIdx.y * 32;
    const int tx = threadIdx.x, ty = threadIdx.y;
    #pragma unroll
    for (int r = 0; r < 4; r++) {
        const int k = k0 + ty + 8 * r;
        const int c = c0 + tx;
        tile[ty + 8 * r][tx] = (k < II) ? Wx[(size_t)k * NNP + c]
                                        : Wh[(size_t)(k - II) * NNP + c];
    }
    __syncthreads();
    #pragma unroll
    for (int r = 0; r < 4; r++) {
        const int c = c0 + ty + 8 * r;
        const int g = c >> 10;
        const int j = c & 1023;
        const int np = 4 * j + g;
        g_Wt[(size_t)np * KK + k0 + tx] = __float2half_rn(tile[tx][ty + 8 * r]);
    }
}

// ------------------------------------------------------------ GEMM kernel ---
__global__ __launch_bounds__(THREADS, 2) void lstm_gemm_kernel(
    const float* __restrict__ cin, const float* __restrict__ bx,
    float* __restrict__ out, int write_c) {
    extern __shared__ char dynsmem[];
    const uint32_t sbase = smem_u32(dynsmem);

    const int tid = threadIdx.x;
    const int wid = tid >> 5;
    const int lane = tid & 31;
    const int tn = blockIdx.x;       // N tile (0..31), 128 packed cols
    const int tm = blockIdx.y;       // M tile (0..63)
    const int row0 = tm * BM;
    const int n0 = tn * BN;

    float acc[4][8][4] = {};          // warp tile 64x64

    // ---- cp.async stage issue: rows of 64 fp16 = 128B, XOR-16B swizzle ----
    auto issue_stage = [&](int kc) {
        if (kc < NCHUNK) {
            const uint32_t sa = sbase + (kc % NSTAGE) * STAGE_BYTES;
            const uint32_t sb = sa + ASTAGE_BYTES;
            const __half* gA = g_At + (size_t)row0 * KK + kc * BK;
            #pragma unroll
            for (int i = 0; i < 8; i++) {
                const int idx = tid + THREADS * i;   // 0..1023 (128 rows x 8 units)
                const int r = idx >> 3, uu = idx & 7;
                const uint32_t dst = sa + r * 128 + ((uu ^ (r & 7)) << 4);
                cp_async16(dst, gA + (size_t)r * KK + uu * 8);
            }
            const __half* gB = g_Wt + (size_t)n0 * KK + kc * BK;
            #pragma unroll
            for (int i = 0; i < 8; i++) {
                const int idx = tid + THREADS * i;   // 0..1023 (128 rows x 8 units)
                const int r = idx >> 3, uu = idx & 7;
                const uint32_t dst = sb + r * 128 + ((uu ^ (r & 7)) << 4);
                cp_async16(dst, gB + (size_t)r * KK + uu * 8);
            }
        }
        cp_commit();
    };

    issue_stage(0);
    issue_stage(1);

    const int wm0 = (wid >> 1) * 64;   // warp M origin (0 or 64)
    const int wn0 = (wid & 1) * 64;    // warp N origin (0 or 64)
    const int lsel = lane >> 3;        // ldmatrix matrix id (0..3)
    const int lrow8 = lane & 7;        // row within 8x8 matrix

    // fragment loader for one K16 step s (double-buffered by caller)
    auto load_frags = [&](uint32_t sa, uint32_t sb, int s,
                          uint32_t (*afr)[4], uint32_t (*bfr)[4]) {
        #pragma unroll
        for (int mi = 0; mi < 4; mi++) {
            const int r = wm0 + mi * 16 + (lsel & 1) * 8 + lrow8;
            const uint32_t ku = (uint32_t)(s * 2 + (lsel >> 1));
            ldmatrix_x4(afr[mi], sa + r * 128 + ((ku ^ (uint32_t)(r & 7)) << 4));
        }
        #pragma unroll
        for (int fp = 0; fp < 4; fp++) {
            const int rn = wn0 + fp * 16 + (lsel >> 1) * 8 + lrow8;
            const uint32_t ku = (uint32_t)(s * 2 + (lsel & 1));
            ldmatrix_x4(bfr[fp], sb + rn * 128 + ((ku ^ (uint32_t)(rn & 7)) << 4));
        }
    };

    #pragma unroll 1
    for (int kc = 0; kc < NCHUNK; kc++) {
        cp_wait1();
        __syncthreads();
        issue_stage(kc + 2);

        const uint32_t sa = sbase + (kc % NSTAGE) * STAGE_BYTES;
        const uint32_t sb = sa + ASTAGE_BYTES;

        uint32_t afr[2][4][4];
        uint32_t bfr[2][4][4];
        load_frags(sa, sb, 0, afr[0], bfr[0]);
        #pragma unroll
        for (int s = 0; s < 4; s++) {           // 4 K-steps of 16 fp16
            const int cur = s & 1;
            if (s < 3) load_frags(sa, sb, s + 1, afr[cur ^ 1], bfr[cur ^ 1]);
            #pragma unroll
            for (int mi = 0; mi < 4; mi++)
                #pragma unroll
                for (int f = 0; f < 8; f++)
                    mma_fp16(acc[mi][f], afr[cur][mi], &bfr[cur][f >> 1][(f & 1) * 2]);
        }
    }

    __syncthreads();   // pipeline stages dead; reuse smem for output staging

    // ---- fused LSTM epilogue ----
    float* smf = reinterpret_cast<float*>(dynsmem);   // h_s[128][33], c_s[128][33]
    const int odd = lane & 1;
    #pragma unroll
    for (int mi = 0; mi < 4; mi++) {
        #pragma unroll
        for (int f = 0; f < 8; f++) {
            const float c0 = acc[mi][f][0], c1 = acc[mi][f][1];
            const float c2 = acc[mi][f][2], c3 = acc[mi][f][3];
            const float x0 = __shfl_xor_sync(0xffffffffu, c0, 1);
            const float x1 = __shfl_xor_sync(0xffffffffu, c1, 1);
            const float x2 = __shfl_xor_sync(0xffffffffu, c2, 1);
            const float x3 = __shfl_xor_sync(0xffffffffu, c3, 1);
            // even lane: own (i,f), partner's (g,o); odd lane: row+8, own (g,o)
            const int lrow = wm0 + mi * 16 + (lane >> 2) + (odd ? 8 : 0);
            const int jc = (wn0 >> 2) + f * 2 + ((lane & 3) >> 1);  // 0..31
            const int j = tn * 32 + jc;
            float gi = (odd ? x2 : c0) + bx[j];
            float gf = (odd ? x3 : c1) + bx[HH + j];
            float gg = (odd ? c2 : x0) + bx[2 * HH + j];
            float go = (odd ? c3 : x1) + bx[3 * HH + j];
            const float iv = sigmoid_f(gi);
            const float fv = sigmoid_f(gf);
            const float gv = tanh_f(gg);
            const float ov = sigmoid_f(go);
            const float cn = fv * cin[(size_t)(row0 + lrow) * HH + j] + iv * gv;
            const float hn = ov * tanh_f(cn);
            smf[lrow * 33 + jc] = hn;
            smf[128 * 33 + lrow * 33 + jc] = cn;
        }
    }
    __syncthreads();

    // coalesced writeback (128 rows x 32 cols)
    #pragma unroll 1
    for (int i = tid; i < 128 * 32; i += THREADS) {
        const int r = i >> 5, jj = i & 31;
        out[(size_t)(row0 + r) * HH + tn * 32 + jj] = smf[r * 33 + jj];
    }
    if (write_c) {
        #pragma unroll 1
        for (int i = tid; i < 128 * 32; i += THREADS) {
            const int r = i >> 5, jj = i & 31;
            out[(size_t)BB * HH + (size_t)(row0 + r) * HH + tn * 32 + jj] =
                smf[128 * 33 + r * 33 + jj];
        }
    }
}

// ------------------------------------------------------------------ launch ---
extern "C" void kernel_launch(void* const* d_in, const int* in_sizes, int n_in,
                              void* d_out, int out_size) {
    const float* x  = (const float*)d_in[0];
    const float* h  = (const float*)d_in[1];
    const float* c  = (const float*)d_in[2];
    const float* Wx = (const float*)d_in[3];
    const float* bx = (const float*)d_in[4];
    const float* Wh = (const float*)d_in[5];
    float* out = (float*)d_out;
    (void)in_sizes; (void)n_in;

    const int write_c = (out_size >= 2 * BB * HH) ? 1 : 0;

    // 1) pack operands to fp16 (W also transposed + gate-interleaved)
    pack_a_kernel<<<(BB * (KK / 8)) / 256, 256>>>(x, h);
    pack_w_kernel<<<dim3(KK / 32, NNP / 32), dim3(32, 8)>>>(Wx, Wh);

    // 2) fp16 mma.sync GEMM with fused LSTM epilogue (2 CTAs/SM)
    static int attr_set = 0;
    if (!attr_set) {
        cudaFuncSetAttribute(lstm_gemm_kernel,
                             cudaFuncAttributeMaxDynamicSharedMemorySize, DYN_SMEM);
        attr_set = 1;
    }
    lstm_gemm_kernel<<<dim3(NNP / BN, BB / BM), THREADS, DYN_SMEM>>>(c, bx, out, write_c);
}

// round 6
// speedup vs baseline: 2.7314x; 1.3026x over previous
#include <cuda_runtime.h>
#include <cuda_fp16.h>
#include <cstdint>
#include <cstddef>

// Problem sizes
#define BB   8192
#define II   1024
#define HH   1024
#define KK   2048          // I + H
#define NNP  4096          // 4*H packed (gate-interleaved)
// GEMM tiling: CTA 128x128, 4 warps of 64x64, 2 CTAs/SM
#define BM   128
#define BN   128
#define BK   64            // fp16 elems per chunk (= 128 bytes per row)
#define NCHUNK (KK / BK)   // 32
#define THREADS 128
#define NSTAGE 3
#define ASTAGE_BYTES (BM * BK * 2)          // 16384
#define BSTAGE_BYTES (BN * BK * 2)          // 16384
#define STAGE_BYTES  (ASTAGE_BYTES + BSTAGE_BYTES)   // 32768
#define DYN_SMEM (NSTAGE * STAGE_BYTES)              // 98304

// Packed fp16 operands
__device__ __half g_At[(size_t)BB * KK];   // [m][k] rows of [x | h]
__device__ __half g_Wt[(size_t)NNP * KK];  // [np][k], np = 4*j + gate

// ---------------------------------------------------------------- helpers ---
__device__ __forceinline__ uint32_t smem_u32(const void* p) {
    uint32_t a;
    asm("{ .reg .u64 t; cvta.to.shared.u64 t, %1; cvt.u32.u64 %0, t; }"
        : "=r"(a) : "l"(p));
    return a;
}
__device__ __forceinline__ void cp_async16(uint32_t saddr, const void* gaddr) {
    asm volatile("cp.async.cg.shared.global [%0], [%1], 16;"
                 :: "r"(saddr), "l"(gaddr) : "memory");
}
__device__ __forceinline__ void cp_commit() {
    asm volatile("cp.async.commit_group;" ::: "memory");
}
__device__ __forceinline__ void cp_wait1() {
    asm volatile("cp.async.wait_group 1;" ::: "memory");
}
__device__ __forceinline__ void cp_wait0() {
    asm volatile("cp.async.wait_group 0;" ::: "memory");
}
__device__ __forceinline__ void ldmatrix_x4(uint32_t* r, uint32_t addr) {
    asm volatile("ldmatrix.sync.aligned.m8n8.x4.shared.b16 {%0,%1,%2,%3}, [%4];"
                 : "=r"(r[0]), "=r"(r[1]), "=r"(r[2]), "=r"(r[3]) : "r"(addr));
}
__device__ __forceinline__ void mma_fp16(float* d, const uint32_t* a, const uint32_t* b) {
    asm volatile(
        "mma.sync.aligned.m16n8k16.row.col.f32.f16.f16.f32 "
        "{%0,%1,%2,%3}, {%4,%5,%6,%7}, {%8,%9}, {%0,%1,%2,%3};"
        : "+f"(d[0]), "+f"(d[1]), "+f"(d[2]), "+f"(d[3])
        : "r"(a[0]), "r"(a[1]), "r"(a[2]), "r"(a[3]), "r"(b[0]), "r"(b[1]));
}
__device__ __forceinline__ float tanh_fast(float x) {
    float y;
    asm("tanh.approx.f32 %0, %1;" : "=f"(y) : "f"(x));
    return y;
}
__device__ __forceinline__ float sigmoid_fast(float v) {
    return fmaf(0.5f, tanh_fast(0.5f * v), 0.5f);
}

// --------------------------------------------------------- fused pack kernel
// blocks [0, PACKA_BLOCKS): A pack; blocks [PACKA_BLOCKS, ...): W pack tiles
#define PACKA_BLOCKS (BB * (KK / 8) / 256)          // 8192
#define PACKW_BLOCKS ((KK / 64) * (NNP / 32))       // 4096
__global__ void pack_fused_kernel(const float* __restrict__ x,
                                  const float* __restrict__ h,
                                  const float* __restrict__ Wx,
                                  const float* __restrict__ Wh) {
    __shared__ float tile[32][65];
    const int tid = threadIdx.x;
    if (blockIdx.x < PACKA_BLOCKS) {
        // ---- A pack: g_At[m][k] = fp16( k<1024 ? x : h ) ----
        const int u = blockIdx.x * 256 + tid;     // 8-elem unit
        const int row = u >> 8;                   // 256 units per row
        const int k0 = (u & 255) * 8;
        const float* src = (k0 < II) ? (x + (size_t)row * II + k0)
                                     : (h + (size_t)row * HH + (k0 - II));
        const float4 v0 = *reinterpret_cast<const float4*>(src);
        const float4 v1 = *reinterpret_cast<const float4*>(src + 4);
        __half2 o[4];
        o[0] = __floats2half2_rn(v0.x, v0.y);
        o[1] = __floats2half2_rn(v0.z, v0.w);
        o[2] = __floats2half2_rn(v1.x, v1.y);
        o[3] = __floats2half2_rn(v1.z, v1.w);
        *reinterpret_cast<uint4*>(&g_At[(size_t)row * KK + k0]) =
            *reinterpret_cast<const uint4*>(o);
    } else {
        // ---- W pack: tile 64k x 32c, write coalesced half2 rows ----
        const int wb = blockIdx.x - PACKA_BLOCKS;
        const int k0 = (wb & 31) * 64;            // 32 k-tiles
        const int c0 = (wb >> 5) * 32;            // 128 c-tiles
        #pragma unroll
        for (int i = 0; i < 8; i++) {
            const int idx = tid + 256 * i;        // 0..2047
            const int cl = idx & 31;
            const int kl = idx >> 5;              // 0..63
            const int k = k0 + kl;
            const int c = c0 + cl;
            tile[cl][kl] = (k < II) ? Wx[(size_t)k * NNP + c]
                                    : Wh[(size_t)(k - II) * NNP + c];
        }
        __syncthreads();
        #pragma unroll
        for (int i = 0; i < 4; i++) {
            const int idx = tid + 256 * i;        // 0..1023
            const int k2 = idx & 31;              // half2 unit within row
            const int cl = idx >> 5;              // 0..31
            const int c = c0 + cl;
            const int g = c >> 10;
            const int j = c & 1023;
            const int np = 4 * j + g;
            const __half2 hv = __floats2half2_rn(tile[cl][2 * k2], tile[cl][2 * k2 + 1]);
            *reinterpret_cast<__half2*>(&g_Wt[(size_t)np * KK + k0 + 2 * k2]) = hv;
        }
    }
}

// ------------------------------------------------------------ GEMM kernel ---
__global__ __launch_bounds__(THREADS, 2) void lstm_gemm_kernel(
    const float* __restrict__ cin, const float* __restrict__ bx,
    float* __restrict__ out, int write_c) {
    extern __shared__ char dynsmem[];
    const uint32_t sbase = smem_u32(dynsmem);

    const int tid = threadIdx.x;
    const int wid = tid >> 5;
    const int lane = tid & 31;
    const int tn = blockIdx.x;       // N tile (0..31), 128 packed cols
    const int tm = blockIdx.y;       // M tile (0..63)
    const int row0 = tm * BM;
    const int n0 = tn * BN;

    float acc[4][8][4] = {};          // warp tile 64x64

    // ---- cp.async stage issue; kc==NCHUNK slot prefetches cin into stage 2 ----
    auto issue_stage = [&](int kc) {
        if (kc < NCHUNK) {
            const uint32_t sa = sbase + (kc % NSTAGE) * STAGE_BYTES;
            const uint32_t sb = sa + ASTAGE_BYTES;
            const __half* gA = g_At + (size_t)row0 * KK + kc * BK;
            #pragma unroll
            for (int i = 0; i < 8; i++) {
                const int idx = tid + THREADS * i;   // 0..1023 (128 rows x 8 units)
                const int r = idx >> 3, uu = idx & 7;
                const uint32_t dst = sa + r * 128 + ((uu ^ (r & 7)) << 4);
                cp_async16(dst, gA + (size_t)r * KK + uu * 8);
            }
            const __half* gB = g_Wt + (size_t)n0 * KK + kc * BK;
            #pragma unroll
            for (int i = 0; i < 8; i++) {
                const int idx = tid + THREADS * i;
                const int r = idx >> 3, uu = idx & 7;
                const uint32_t dst = sb + r * 128 + ((uu ^ (r & 7)) << 4);
                cp_async16(dst, gB + (size_t)r * KK + uu * 8);
            }
        } else if (kc == NCHUNK) {
            // cin tile [128][32] -> stage-2 region as float[128][36] (pad vs banks)
            const uint32_t cbase = sbase + 2 * STAGE_BYTES;
            const float* gC = cin + (size_t)row0 * HH + tn * 32;
            #pragma unroll
            for (int i = 0; i < 8; i++) {
                const int v = tid + THREADS * i;     // 0..1023 (128 rows x 8 units)
                const int r = v >> 3, uu = v & 7;
                cp_async16(cbase + r * 144 + uu * 16, gC + (size_t)r * HH + uu * 4);
            }
        }
        cp_commit();
    };

    issue_stage(0);
    issue_stage(1);

    const int wm0 = (wid >> 1) * 64;   // warp M origin (0 or 64)
    const int wn0 = (wid & 1) * 64;    // warp N origin (0 or 64)
    const int lsel = lane >> 3;        // ldmatrix matrix id (0..3)
    const int lrow8 = lane & 7;        // row within 8x8 matrix

    auto load_frags = [&](uint32_t sa, uint32_t sb, int s,
                          uint32_t (*afr)[4], uint32_t (*bfr)[4]) {
        #pragma unroll
        for (int mi = 0; mi < 4; mi++) {
            const int r = wm0 + mi * 16 + (lsel & 1) * 8 + lrow8;
            const uint32_t ku = (uint32_t)(s * 2 + (lsel >> 1));
            ldmatrix_x4(afr[mi], sa + r * 128 + ((ku ^ (uint32_t)(r & 7)) << 4));
        }
        #pragma unroll
        for (int fp = 0; fp < 4; fp++) {
            const int rn = wn0 + fp * 16 + (lsel >> 1) * 8 + lrow8;
            const uint32_t ku = (uint32_t)(s * 2 + (lsel & 1));
            ldmatrix_x4(bfr[fp], sb + rn * 128 + ((ku ^ (uint32_t)(rn & 7)) << 4));
        }
    };

    #pragma unroll 1
    for (int kc = 0; kc < NCHUNK; kc++) {
        cp_wait1();
        __syncthreads();
        issue_stage(kc + 2);   // kc=30 issues the cin prefetch; kc=31 empty commit

        const uint32_t sa = sbase + (kc % NSTAGE) * STAGE_BYTES;
        const uint32_t sb = sa + ASTAGE_BYTES;

        uint32_t afr[2][4][4];
        uint32_t bfr[2][4][4];
        load_frags(sa, sb, 0, afr[0], bfr[0]);
        #pragma unroll
        for (int s = 0; s < 4; s++) {           // 4 K-steps of 16 fp16
            const int cur = s & 1;
            if (s < 3) load_frags(sa, sb, s + 1, afr[cur ^ 1], bfr[cur ^ 1]);
            #pragma unroll
            for (int mi = 0; mi < 4; mi++)
                #pragma unroll
                for (int f = 0; f < 8; f++)
                    mma_fp16(acc[mi][f], afr[cur][mi], &bfr[cur][f >> 1][(f & 1) * 2]);
        }
    }

    cp_wait0();        // cin prefetch complete
    __syncthreads();   // stages 0/1 dead; reuse for output staging

    // ---- fused LSTM epilogue ----
    float* smf = reinterpret_cast<float*>(dynsmem);   // h_s[128][33], c_s[128][33]
    const float* cin_s = reinterpret_cast<const float*>(dynsmem + 2 * STAGE_BYTES);
    const int odd = lane & 1;
    #pragma unroll
    for (int mi = 0; mi < 4; mi++) {
        #pragma unroll
        for (int f = 0; f < 8; f++) {
            const float c0 = acc[mi][f][0], c1 = acc[mi][f][1];
            const float c2 = acc[mi][f][2], c3 = acc[mi][f][3];
            const float x0 = __shfl_xor_sync(0xffffffffu, c0, 1);
            const float x1 = __shfl_xor_sync(0xffffffffu, c1, 1);
            const float x2 = __shfl_xor_sync(0xffffffffu, c2, 1);
            const float x3 = __shfl_xor_sync(0xffffffffu, c3, 1);
            // even lane: own (i,f), partner's (g,o); odd lane: row+8, own (g,o)
            const int lrow = wm0 + mi * 16 + (lane >> 2) + (odd ? 8 : 0);
            const int jc = (wn0 >> 2) + f * 2 + ((lane & 3) >> 1);  // 0..31
            const int j = tn * 32 + jc;
            float gi = (odd ? x2 : c0) + bx[j];
            float gf = (odd ? x3 : c1) + bx[HH + j];
            float gg = (odd ? c2 : x0) + bx[2 * HH + j];
            float go = (odd ? c3 : x1) + bx[3 * HH + j];
            const float iv = sigmoid_fast(gi);
            const float fv = sigmoid_fast(gf);
            const float gv = tanh_fast(gg);
            const float ov = sigmoid_fast(go);
            const float cn = fv * cin_s[lrow * 36 + jc] + iv * gv;
            const float hn = ov * tanh_fast(cn);
            smf[lrow * 33 + jc] = hn;
            smf[128 * 33 + lrow * 33 + jc] = cn;
        }
    }
    __syncthreads();

    // coalesced writeback (128 rows x 32 cols)
    #pragma unroll 1
    for (int i = tid; i < 128 * 32; i += THREADS) {
        const int r = i >> 5, jj = i & 31;
        out[(size_t)(row0 + r) * HH + tn * 32 + jj] = smf[r * 33 + jj];
    }
    if (write_c) {
        #pragma unroll 1
        for (int i = tid; i < 128 * 32; i += THREADS) {
            const int r = i >> 5, jj = i & 31;
            out[(size_t)BB * HH + (size_t)(row0 + r) * HH + tn * 32 + jj] =
                smf[128 * 33 + r * 33 + jj];
        }
    }
}

// ------------------------------------------------------------------ launch ---
extern "C" void kernel_launch(void* const* d_in, const int* in_sizes, int n_in,
                              void* d_out, int out_size) {
    const float* x  = (const float*)d_in[0];
    const float* h  = (const float*)d_in[1];
    const float* c  = (const float*)d_in[2];
    const float* Wx = (const float*)d_in[3];
    const float* bx = (const float*)d_in[4];
    const float* Wh = (const float*)d_in[5];
    float* out = (float*)d_out;
    (void)in_sizes; (void)n_in;

    const int write_c = (out_size >= 2 * BB * HH) ? 1 : 0;

    // 1) fused pack: A->fp16, W->fp16 transposed + gate-interleaved
    pack_fused_kernel<<<PACKA_BLOCKS + PACKW_BLOCKS, 256>>>(x, h, Wx, Wh);

    // 2) fp16 mma.sync GEMM with fused LSTM epilogue (2 CTAs/SM)
    static int attr_set = 0;
    if (!attr_set) {
        cudaFuncSetAttribute(lstm_gemm_kernel,
                             cudaFuncAttributeMaxDynamicSharedMemorySize, DYN_SMEM);
        attr_set = 1;
    }
    lstm_gemm_kernel<<<dim3(NNP / BN, BB / BM), THREADS, DYN_SMEM>>>(c, bx, out, write_c);
}

// round 8
// speedup vs baseline: 2.7856x; 1.0199x over previous
#include <cuda_runtime.h>
#include <cuda_fp16.h>
#include <cstdint>
#include <cstddef>

// Problem sizes
#define BB   8192
#define II   1024
#define HH   1024
#define KK   2048          // I + H
#define NNP  4096          // 4*H packed (gate-interleaved)
// GEMM tiling: CTA 128x128, 4 warps of 64x64, 2 CTAs/SM
#define BM   128
#define BN   128
#define BK   64            // fp16 elems per chunk (= 128 bytes per row)
#define NCHUNK (KK / BK)   // 32
#define THREADS 128
#define NSTAGE 3
#define ASTAGE_BYTES (BM * BK * 2)          // 16384
#define BSTAGE_BYTES (BN * BK * 2)          // 16384
#define STAGE_BYTES  (ASTAGE_BYTES + BSTAGE_BYTES)   // 32768
#define DYN_SMEM (NSTAGE * STAGE_BYTES)              // 98304

// Packed fp16 operands
__device__ __half g_At[(size_t)BB * KK];   // [m][k] rows of [x | h]
__device__ __half g_Wt[(size_t)NNP * KK];  // [np][k], np = 4*j + gate

// ---------------------------------------------------------------- helpers ---
__device__ __forceinline__ uint32_t smem_u32(const void* p) {
    uint32_t a;
    asm("{ .reg .u64 t; cvta.to.shared.u64 t, %1; cvt.u32.u64 %0, t; }"
        : "=r"(a) : "l"(p));
    return a;
}
__device__ __forceinline__ void cp_async16(uint32_t saddr, const void* gaddr) {
    asm volatile("cp.async.cg.shared.global [%0], [%1], 16;"
                 :: "r"(saddr), "l"(gaddr) : "memory");
}
__device__ __forceinline__ void cp_async_arrive_noinc(uint32_t mbar) {
    // thread's prior cp.asyncs arrive on mbar when complete (count pre-baked)
    asm volatile("cp.async.mbarrier.arrive.noinc.shared.b64 [%0];"
                 :: "r"(mbar) : "memory");
}
__device__ __forceinline__ void mbar_init(uint32_t addr, uint32_t cnt) {
    asm volatile("mbarrier.init.shared.b64 [%0], %1;" :: "r"(addr), "r"(cnt) : "memory");
}
__device__ __forceinline__ void mbar_arrive(uint32_t addr) {
    asm volatile("mbarrier.arrive.shared.b64 _, [%0];" :: "r"(addr) : "memory");
}
__device__ __forceinline__ void mbar_wait(uint32_t addr, uint32_t parity) {
    asm volatile(
        "{\n\t"
        ".reg .pred P1;\n\t"
        "LAB_WAIT_%=:\n\t"
        "mbarrier.try_wait.parity.acquire.cta.shared::cta.b64 P1, [%0], %1, 0x989680;\n\t"
        "@P1 bra LAB_DONE_%=;\n\t"
        "bra LAB_WAIT_%=;\n\t"
        "LAB_DONE_%=:\n\t"
        "}"
        :: "r"(addr), "r"(parity) : "memory");
}
__device__ __forceinline__ void ldmatrix_x4(uint32_t* r, uint32_t addr) {
    asm volatile("ldmatrix.sync.aligned.m8n8.x4.shared.b16 {%0,%1,%2,%3}, [%4];"
                 : "=r"(r[0]), "=r"(r[1]), "=r"(r[2]), "=r"(r[3]) : "r"(addr));
}
__device__ __forceinline__ void mma_fp16(float* d, const uint32_t* a, const uint32_t* b) {
    asm volatile(
        "mma.sync.aligned.m16n8k16.row.col.f32.f16.f16.f32 "
        "{%0,%1,%2,%3}, {%4,%5,%6,%7}, {%8,%9}, {%0,%1,%2,%3};"
        : "+f"(d[0]), "+f"(d[1]), "+f"(d[2]), "+f"(d[3])
        : "r"(a[0]), "r"(a[1]), "r"(a[2]), "r"(a[3]), "r"(b[0]), "r"(b[1]));
}
__device__ __forceinline__ float tanh_fast(float x) {
    float y;
    asm("tanh.approx.f32 %0, %1;" : "=f"(y) : "f"(x));
    return y;
}
__device__ __forceinline__ float sigmoid_fast(float v) {
    return fmaf(0.5f, tanh_fast(0.5f * v), 0.5f);
}

// --------------------------------------------------------- fused pack kernel
#define PACKA_BLOCKS (BB * (KK / 8) / 256)          // 8192
#define PACKW_BLOCKS ((KK / 64) * (NNP / 32))       // 4096
__global__ void pack_fused_kernel(const float* __restrict__ x,
                                  const float* __restrict__ h,
                                  const float* __restrict__ Wx,
                                  const float* __restrict__ Wh) {
    __shared__ float tile[32][65];
    const int tid = threadIdx.x;
    if (blockIdx.x < PACKA_BLOCKS) {
        // ---- A pack: g_At[m][k] = fp16( k<1024 ? x : h ) ----
        const int u = blockIdx.x * 256 + tid;     // 8-elem unit
        const int row = u >> 8;                   // 256 units per row
        const int k0 = (u & 255) * 8;
        const float* src = (k0 < II) ? (x + (size_t)row * II + k0)
                                     : (h + (size_t)row * HH + (k0 - II));
        const float4 v0 = *reinterpret_cast<const float4*>(src);
        const float4 v1 = *reinterpret_cast<const float4*>(src + 4);
        __half2 o[4];
        o[0] = __floats2half2_rn(v0.x, v0.y);
        o[1] = __floats2half2_rn(v0.z, v0.w);
        o[2] = __floats2half2_rn(v1.x, v1.y);
        o[3] = __floats2half2_rn(v1.z, v1.w);
        *reinterpret_cast<uint4*>(&g_At[(size_t)row * KK + k0]) =
            *reinterpret_cast<const uint4*>(o);
    } else {
        // ---- W pack: tile 64k x 32c, write coalesced half2 rows ----
        const int wb = blockIdx.x - PACKA_BLOCKS;
        const int k0 = (wb & 31) * 64;            // 32 k-tiles
        const int c0 = (wb >> 5) * 32;            // 128 c-tiles
        #pragma unroll
        for (int i = 0; i < 8; i++) {
            const int idx = tid + 256 * i;        // 0..2047
            const int cl = idx & 31;
            const int kl = idx >> 5;              // 0..63
            const int k = k0 + kl;
            const int c = c0 + cl;
            tile[cl][kl] = (k < II) ? Wx[(size_t)k * NNP + c]
                                    : Wh[(size_t)(k - II) * NNP + c];
        }
        __syncthreads();
        #pragma unroll
        for (int i = 0; i < 4; i++) {
            const int idx = tid + 256 * i;        // 0..1023
            const int k2 = idx & 31;              // half2 unit within row
            const int cl = idx >> 5;              // 0..31
            const int c = c0 + cl;
            const int g = c >> 10;
            const int j = c & 1023;
            const int np = 4 * j + g;
            const __half2 hv = __floats2half2_rn(tile[cl][2 * k2], tile[cl][2 * k2 + 1]);
            *reinterpret_cast<__half2*>(&g_Wt[(size_t)np * KK + k0 + 2 * k2]) = hv;
        }
    }
}

// ------------------------------------------------------------ GEMM kernel ---
// mbarrier-decoupled cp.async pipeline: no __syncthreads in the mainloop.
// mbars: [0..2] full[s] (cnt 128, async arrivals), [3..5] free[s] (cnt 4),
//        [6] cin ready (cnt 128, async arrivals)
__global__ __launch_bounds__(THREADS, 2) void lstm_gemm_kernel(
    const float* __restrict__ cin, const float* __restrict__ bx,
    float* __restrict__ out, int write_c) {
    extern __shared__ char dynsmem[];
    __shared__ __align__(8) uint64_t s_mb[7];
    const uint32_t sbase = smem_u32(dynsmem);
    const uint32_t mb0 = smem_u32(&s_mb[0]);

    const int tid = threadIdx.x;
    const int wid = tid >> 5;
    const int lane = tid & 31;
    const int tn = blockIdx.x;       // N tile (0..31), 128 packed cols
    const int tm = blockIdx.y;       // M tile (0..63)
    const int row0 = tm * BM;
    const int n0 = tn * BN;

    if (tid == 0) {
        #pragma unroll
        for (int s = 0; s < 3; s++) mbar_init(mb0 + 8 * s, 128);        // full
        #pragma unroll
        for (int s = 0; s < 3; s++) mbar_init(mb0 + 8 * (3 + s), 4);    // free
        mbar_init(mb0 + 8 * 6, 128);                                    // cin
    }
    __syncthreads();

    float acc[4][8][4] = {};          // warp tile 64x64

    // ---- producer: fill kf (stage kf%3); kf==NCHUNK fills cin into stage 2 ----
    auto producer = [&](int kf) {
        if (kf < NCHUNK) {
            const int st = kf % NSTAGE;
            if (kf >= NSTAGE) mbar_wait(mb0 + 8 * (3 + st), (uint32_t)((kf / NSTAGE - 1) & 1));
            const uint32_t sa = sbase + st * STAGE_BYTES;
            const uint32_t sb = sa + ASTAGE_BYTES;
            const __half* gA = g_At + (size_t)row0 * KK + kf * BK;
            #pragma unroll
            for (int i = 0; i < 8; i++) {
                const int idx = tid + THREADS * i;   // 0..1023 (128 rows x 8 units)
                const int r = idx >> 3, uu = idx & 7;
                cp_async16(sa + r * 128 + ((uu ^ (r & 7)) << 4),
                           gA + (size_t)r * KK + uu * 8);
            }
            const __half* gB = g_Wt + (size_t)n0 * KK + kf * BK;
            #pragma unroll
            for (int i = 0; i < 8; i++) {
                const int idx = tid + THREADS * i;
                const int r = idx >> 3, uu = idx & 7;
                cp_async16(sb + r * 128 + ((uu ^ (r & 7)) << 4),
                           gB + (size_t)r * KK + uu * 8);
            }
            cp_async_arrive_noinc(mb0 + 8 * st);
        } else if (kf == NCHUNK) {
            // cin tile [128][32] f32 into stage-2 region (dead after use kc=29)
            mbar_wait(mb0 + 8 * (3 + 2), (uint32_t)((NCHUNK / NSTAGE - 1) & 1));  // phase 9 -> parity 1
            const uint32_t cb = sbase + 2 * STAGE_BYTES;
            const float* gC = cin + (size_t)row0 * HH + tn * 32;
            #pragma unroll
            for (int i = 0; i < 8; i++) {
                const int v = tid + THREADS * i;     // 0..1023 (128 rows x 8 units)
                const int r = v >> 3, uu = v & 7;
                cp_async16(cb + r * 128 + ((uu ^ (r & 7)) << 4),
                           gC + (size_t)r * HH + uu * 4);
            }
            cp_async_arrive_noinc(mb0 + 8 * 6);
        }
    };

    producer(0);
    producer(1);

    const int wm0 = (wid >> 1) * 64;   // warp M origin (0 or 64)
    const int wn0 = (wid & 1) * 64;    // warp N origin (0 or 64)
    const int lsel = lane >> 3;        // ldmatrix matrix id (0..3)
    const int lrow8 = lane & 7;        // row within 8x8 matrix

    auto load_frags = [&](uint32_t sa, uint32_t sb, int s,
                          uint32_t (*afr)[4], uint32_t (*bfr)[4]) {
        #pragma unroll
        for (int mi = 0; mi < 4; mi++) {
            const int r = wm0 + mi * 16 + (lsel & 1) * 8 + lrow8;
            const uint32_t ku = (uint32_t)(s * 2 + (lsel >> 1));
            ldmatrix_x4(afr[mi], sa + r * 128 + ((ku ^ (uint32_t)(r & 7)) << 4));
        }
        #pragma unroll
        for (int fp = 0; fp < 4; fp++) {
            const int rn = wn0 + fp * 16 + (lsel >> 1) * 8 + lrow8;
            const uint32_t ku = (uint32_t)(s * 2 + (lsel & 1));
            ldmatrix_x4(bfr[fp], sb + rn * 128 + ((ku ^ (uint32_t)(rn & 7)) << 4));
        }
    };
    auto mma_all = [&](uint32_t (*afr)[4], uint32_t (*bfr)[4]) {
        #pragma unroll
        for (int mi = 0; mi < 4; mi++)
            #pragma unroll
            for (int f = 0; f < 8; f++)
                mma_fp16(acc[mi][f], afr[mi], &bfr[f >> 1][(f & 1) * 2]);
    };

    #pragma unroll 1
    for (int kc = 0; kc < NCHUNK; kc++) {
        const int st = kc % NSTAGE;
        const uint32_t sa = sbase + st * STAGE_BYTES;
        const uint32_t sb = sa + ASTAGE_BYTES;

        mbar_wait(mb0 + 8 * st, (uint32_t)((kc / NSTAGE) & 1));   // data ready

        uint32_t afr[2][4][4];
        uint32_t bfr[2][4][4];
        load_frags(sa, sb, 0, afr[0], bfr[0]);
        // s=0
        load_frags(sa, sb, 1, afr[1], bfr[1]);
        mma_all(afr[0], bfr[0]);
        // producer for kc+2 (free-wait hides under queued MMAs)
        producer(kc + 2);
        // s=1
        load_frags(sa, sb, 2, afr[0], bfr[0]);
        mma_all(afr[1], bfr[1]);
        // s=2 (loads s=3 frags: last reads of this stage)
        load_frags(sa, sb, 3, afr[1], bfr[1]);
        mma_all(afr[0], bfr[0]);
        // s=3: this warp is done reading the stage
        if (lane == 0) mbar_arrive(mb0 + 8 * (3 + st));
        mma_all(afr[1], bfr[1]);
    }

    mbar_wait(mb0 + 8 * 6, 0u);   // cin prefetch complete
    __syncthreads();              // all warps done with stages 0/1 before reuse

    // ---- fused LSTM epilogue ----
    float* smf = reinterpret_cast<float*>(dynsmem);   // h_s[128][33], c_s[128][33]
    const float* cin_s = reinterpret_cast<const float*>(dynsmem + 2 * STAGE_BYTES);
    const int odd = lane & 1;
    #pragma unroll
    for (int mi = 0; mi < 4; mi++) {
        #pragma unroll
        for (int f = 0; f < 8; f++) {
            const float c0 = acc[mi][f][0], c1 = acc[mi][f][1];
            const float c2 = acc[mi][f][2], c3 = acc[mi][f][3];
            const float x0 = __shfl_xor_sync(0xffffffffu, c0, 1);
            const float x1 = __shfl_xor_sync(0xffffffffu, c1, 1);
            const float x2 = __shfl_xor_sync(0xffffffffu, c2, 1);
            const float x3 = __shfl_xor_sync(0xffffffffu, c3, 1);
            // even lane: own (i,f), partner's (g,o); odd lane: row+8, own (g,o)
            const int lrow = wm0 + mi * 16 + (lane >> 2) + (odd ? 8 : 0);
            const int jc = (wn0 >> 2) + f * 2 + ((lane & 3) >> 1);  // 0..31
            const int j = tn * 32 + jc;
            float gi = (odd ? x2 : c0) + bx[j];
            float gf = (odd ? x3 : c1) + bx[HH + j];
            float gg = (odd ? c2 : x0) + bx[2 * HH + j];
            float go = (odd ? c3 : x1) + bx[3 * HH + j];
            const float iv = sigmoid_fast(gi);
            const float fv = sigmoid_fast(gf);
            const float gv = tanh_fast(gg);
            const float ov = sigmoid_fast(go);
            // swizzled cin read (matches cp.async 16B-unit swizzle)
            const int u2 = jc >> 2;
            const float cv = cin_s[lrow * 32 + (((u2 ^ (lrow & 7)) << 2) | (jc & 3))];
            const float cn = fv * cv + iv * gv;
            const float hn = ov * tanh_fast(cn);
            smf[lrow * 33 + jc] = hn;
            smf[128 * 33 + lrow * 33 + jc] = cn;
        }
    }
    __syncthreads();

    // coalesced writeback (128 rows x 32 cols)
    #pragma unroll 1
    for (int i = tid; i < 128 * 32; i += THREADS) {
        const int r = i >> 5, jj = i & 31;
        out[(size_t)(row0 + r) * HH + tn * 32 + jj] = smf[r * 33 + jj];
    }
    if (write_c) {
        #pragma unroll 1
        for (int i = tid; i < 128 * 32; i += THREADS) {
            const int r = i >> 5, jj = i & 31;
            out[(size_t)BB * HH + (size_t)(row0 + r) * HH + tn * 32 + jj] =
                smf[128 * 33 + r * 33 + jj];
        }
    }
}

// ------------------------------------------------------------------ launch ---
extern "C" void kernel_launch(void* const* d_in, const int* in_sizes, int n_in,
                              void* d_out, int out_size) {
    const float* x  = (const float*)d_in[0];
    const float* h  = (const float*)d_in[1];
    const float* c  = (const float*)d_in[2];
    const float* Wx = (const float*)d_in[3];
    const float* bx = (const float*)d_in[4];
    const float* Wh = (const float*)d_in[5];
    float* out = (float*)d_out;
    (void)in_sizes; (void)n_in;

    const int write_c = (out_size >= 2 * BB * HH) ? 1 : 0;

    // 1) fused pack: A->fp16, W->fp16 transposed + gate-interleaved
    pack_fused_kernel<<<PACKA_BLOCKS + PACKW_BLOCKS, 256>>>(x, h, Wx, Wh);

    // 2) fp16 mma.sync GEMM, mbarrier-decoupled pipeline, fused LSTM epilogue
    static int attr_set = 0;
    if (!attr_set) {
        cudaFuncSetAttribute(lstm_gemm_kernel,
                             cudaFuncAttributeMaxDynamicSharedMemorySize, DYN_SMEM);
        attr_set = 1;
    }
    lstm_gemm_kernel<<<dim3(NNP / BN, BB / BM), THREADS, DYN_SMEM>>>(c, bx, out, write_c);
}